// round 11
// baseline (speedup 1.0000x reference)
#include <cuda_runtime.h>
#include <cstdint>
#include <math.h>

// Problem constants
#define T_SEQ 2048
#define H     256
#define G3    768          // 3*H gate rows
#define VOUT  32000

// Scan cluster config
#define CLN          8     // cluster size
#define SLICE        32    // hidden units per CTA (H / CLN)
#define SCAN_THREADS 384   // 12 warps; warp w computes rows [8w, 8w+8)

// Scan chunking for GEMM overlap
#define NCHUNK 8
#define TCH    (T_SEQ / NCHUNK)   // 256 steps per chunk

// ---------------------------------------------------------------------------
// Device scratch (static __device__ arrays: allocation-free per harness rules)
// ---------------------------------------------------------------------------
__device__ __align__(16) float g_Xenc[T_SEQ * H];
__device__ __align__(16) float g_Xdec[T_SEQ * H];
__device__ __align__(16) float g_gi_enc[T_SEQ * G3];
__device__ __align__(16) float g_gi_dec[T_SEQ * G3];
__device__ __align__(16) float g_Hs[T_SEQ * H];
__device__ __align__(16) float g_hstate[H];
__device__ __align__(16) float g_sumexp[T_SEQ];

// ---------------------------------------------------------------------------
// PTX helpers
// ---------------------------------------------------------------------------
__device__ __forceinline__ uint32_t cvta_smem(const void* p) {
    return (uint32_t)__cvta_generic_to_shared(p);
}
__device__ __forceinline__ uint32_t mapa_u32(uint32_t laddr, uint32_t rank) {
    uint32_t r;
    asm("mapa.shared::cluster.u32 %0, %1, %2;" : "=r"(r) : "r"(laddr), "r"(rank));
    return r;
}
#define CLUSTER_SYNC_() do { \
    asm volatile("barrier.cluster.arrive.aligned;" ::: "memory"); \
    asm volatile("barrier.cluster.wait.aligned;"   ::: "memory"); \
} while (0)

// packed fp32x2 FMA (Blackwell): d = a*b + c elementwise on 2 packed floats
__device__ __forceinline__ unsigned long long fma2(unsigned long long a,
                                                   unsigned long long b,
                                                   unsigned long long c) {
    unsigned long long d;
    asm("fma.rn.f32x2 %0, %1, %2, %3;" : "=l"(d) : "l"(a), "l"(b), "l"(c));
    return d;
}
__device__ __forceinline__ float2 unpack2(unsigned long long v) {
    float2 r;
    asm("mov.b64 {%0, %1}, %2;" : "=f"(r.x), "=f"(r.y) : "l"(v));
    return r;
}

// fast gates (MUFU-based; rel err ~1e-6, safe vs 1e-3 tolerance)
__device__ __forceinline__ float fsigmoid(float x) {
    return __fdividef(1.f, 1.f + __expf(-x));     // x->-inf: exp=inf -> 0  OK
}
__device__ __forceinline__ float ftanh(float x) {
    float e = __expf(fminf(-2.f * x, 80.f));      // clamp avoids inf/inf NaN
    return (1.f - e) * __fdividef(1.f, 1.f + e);
}

// ---------------------------------------------------------------------------
// 1) Gather embeddings (+ relu for decoder input) and zero the sum-exp accum.
// ---------------------------------------------------------------------------
__global__ void gather_kernel(const int* __restrict__ src, const int* __restrict__ trg,
                              const float* __restrict__ enc_emb,
                              const float* __restrict__ dec_emb)
{
    int t = blockIdx.x;
    int i = threadIdx.x;           // 256 threads
    int s = src[t];
    int d = trg[t];
    g_Xenc[t * H + i] = enc_emb[(size_t)s * H + i];
    float v = dec_emb[(size_t)d * H + i];
    g_Xdec[t * H + i] = v > 0.f ? v : 0.f;
    if (t < T_SEQ / H) g_sumexp[t * H + i] = 0.f;   // 8 blocks zero all 2048 entries
}

// ---------------------------------------------------------------------------
// 2) fp32 GEMM: C[M][N] = A[M][256] * B[N][256]^T + bias[N]
//    128x128 tiles, BK=16, 256 threads, 8x8 micro-tile.
//    do_lse: accumulate per-row sum(exp(c)) into g_sumexp[row0+row].
// ---------------------------------------------------------------------------
__global__ __launch_bounds__(256)
void gemm_kernel(const float* __restrict__ A, const float* __restrict__ B,
                 const float* __restrict__ bias, float* __restrict__ C,
                 int N, int do_lse, int row0)
{
    __shared__ float As[16][132];   // [k][m], padded
    __shared__ float Bs[16][132];   // [k][n], padded

    int tid = threadIdx.x;
    int tx = tid & 15;              // 0..15 : col group (8 cols)
    int ty = tid >> 4;              // 0..15 : row group (8 rows)
    int bm = blockIdx.x * 128;
    int bn = blockIdx.y * 128;

    int lr  = tid >> 1;             // 0..127 : tile row for loads
    int lk8 = (tid & 1) * 8;        // 0 or 8 : k offset for loads

    const float* Ap = A + (size_t)(bm + lr) * 256 + lk8;
    const float* Bp = B + (size_t)(bn + lr) * 256 + lk8;

    float acc[8][8] = {};

    float4 ra0 = *(const float4*)(Ap + 0);
    float4 ra1 = *(const float4*)(Ap + 4);
    float4 rb0 = *(const float4*)(Bp + 0);
    float4 rb1 = *(const float4*)(Bp + 4);

    for (int kb = 0; kb < 256; kb += 16) {
        __syncthreads();
        As[lk8 + 0][lr] = ra0.x; As[lk8 + 1][lr] = ra0.y; As[lk8 + 2][lr] = ra0.z; As[lk8 + 3][lr] = ra0.w;
        As[lk8 + 4][lr] = ra1.x; As[lk8 + 5][lr] = ra1.y; As[lk8 + 6][lr] = ra1.z; As[lk8 + 7][lr] = ra1.w;
        Bs[lk8 + 0][lr] = rb0.x; Bs[lk8 + 1][lr] = rb0.y; Bs[lk8 + 2][lr] = rb0.z; Bs[lk8 + 3][lr] = rb0.w;
        Bs[lk8 + 4][lr] = rb1.x; Bs[lk8 + 5][lr] = rb1.y; Bs[lk8 + 6][lr] = rb1.z; Bs[lk8 + 7][lr] = rb1.w;
        __syncthreads();
        if (kb < 240) {
            ra0 = *(const float4*)(Ap + kb + 16);
            ra1 = *(const float4*)(Ap + kb + 20);
            rb0 = *(const float4*)(Bp + kb + 16);
            rb1 = *(const float4*)(Bp + kb + 20);
        }
#pragma unroll
        for (int kk = 0; kk < 16; kk++) {
            float4 av0 = *(const float4*)&As[kk][ty * 8];
            float4 av1 = *(const float4*)&As[kk][ty * 8 + 4];
            float4 bv0 = *(const float4*)&Bs[kk][tx * 8];
            float4 bv1 = *(const float4*)&Bs[kk][tx * 8 + 4];
            float a[8] = {av0.x, av0.y, av0.z, av0.w, av1.x, av1.y, av1.z, av1.w};
            float b[8] = {bv0.x, bv0.y, bv0.z, bv0.w, bv1.x, bv1.y, bv1.z, bv1.w};
#pragma unroll
            for (int i = 0; i < 8; i++)
#pragma unroll
                for (int j = 0; j < 8; j++)
                    acc[i][j] += a[i] * b[j];
        }
    }

    float4 bb0 = *(const float4*)(bias + bn + tx * 8);
    float4 bb1 = *(const float4*)(bias + bn + tx * 8 + 4);
    float bbv[8] = {bb0.x, bb0.y, bb0.z, bb0.w, bb1.x, bb1.y, bb1.z, bb1.w};

#pragma unroll
    for (int i = 0; i < 8; i++) {
        int row = bm + ty * 8 + i;
        float o[8];
#pragma unroll
        for (int j = 0; j < 8; j++) o[j] = acc[i][j] + bbv[j];
        float4 o0 = {o[0], o[1], o[2], o[3]};
        float4 o1 = {o[4], o[5], o[6], o[7]};
        float* cp = C + (size_t)row * N + bn + tx * 8;
        *(float4*)(cp)     = o0;
        *(float4*)(cp + 4) = o1;
        if (do_lse) {
            // logits bounded by ~16.1 -> max-free sum-exp is safe in fp32
            float s = 0.f;
#pragma unroll
            for (int j = 0; j < 8; j++) s += __expf(o[j]);
            s += __shfl_xor_sync(0xffffffffu, s, 1);
            s += __shfl_xor_sync(0xffffffffu, s, 2);
            s += __shfl_xor_sync(0xffffffffu, s, 4);
            s += __shfl_xor_sync(0xffffffffu, s, 8);
            if (tx == 0) atomicAdd(&g_sumexp[row0 + row], s);
        }
    }
}

// ---------------------------------------------------------------------------
// 3) Sequential GRU scan, single 8-CTA cluster, weights in registers (f32x2).
//    Mapping: warp w -> rows [8w,8w+8); lane l -> row 8w+(l&7), h-segment
//    [64*(l>>3), +64). One accumulator chain per lane (4 interleaved f32x2
//    partials), reduction = 2 shuffles (xor 8, 16). Fast MUFU gates.
//    Sync: barrier.cluster (proven). Chunked [t0,t1) with h persisted in
//    g_hstate so the logits GEMM can overlap on other SMs.
// ---------------------------------------------------------------------------
__shared__ __align__(16) float sh_hb[2 * H];   // replicated h, double buffered
__shared__ float sh_gh[96];                    // row sums (r/z/n x 32 units)
__shared__ float sh_bias[192];                 // [0:96) enc b_hh, [96:192) dec
__shared__ uint32_t sh_pbase[2][CLN];          // remote dest-buffer base addrs

__device__ __forceinline__ void half_step_reg(
    const unsigned long long (&w2)[32], int p, int tid, int l, int w, int seg,
    int unit, float g_r, float g_z, float g_n, int bias_off,
    bool write_hs, bool write_state, int t)
{
    const ulonglong2* hp2 = (const ulonglong2*)(sh_hb + p * H + 64 * seg);
    unsigned long long a0 = 0ull, a1 = 0ull, a2 = 0ull, a3 = 0ull;
#pragma unroll
    for (int i = 0; i < 16; i++) {
        ulonglong2 hv = hp2[i];
        if ((i & 1) == 0) {
            a0 = fma2(w2[2 * i],     hv.x, a0);
            a1 = fma2(w2[2 * i + 1], hv.y, a1);
        } else {
            a2 = fma2(w2[2 * i],     hv.x, a2);
            a3 = fma2(w2[2 * i + 1], hv.y, a3);
        }
    }
    float2 f0 = unpack2(a0), f1 = unpack2(a1), f2 = unpack2(a2), f3 = unpack2(a3);
    float v = ((f0.x + f0.y) + (f1.x + f1.y)) + ((f2.x + f2.y) + (f3.x + f3.y));
    // row total: sum the 4 h-segments (lanes l, l^8, l^16, l^24 share a row)
    v += __shfl_xor_sync(0xffffffffu, v, 8);
    v += __shfl_xor_sync(0xffffffffu, v, 16);
    if (l < 8) sh_gh[8 * w + l] = v;
    __syncthreads();

    if (tid < SLICE) {
        float r = fsigmoid(g_r + sh_gh[tid]      + sh_bias[bias_off + tid]);
        float z = fsigmoid(g_z + sh_gh[32 + tid] + sh_bias[bias_off + 32 + tid]);
        float n = ftanh(g_n + r * (sh_gh[64 + tid] + sh_bias[bias_off + 64 + tid]));
        float hold = sh_hb[p * H + unit];
        float hnew = (1.f - z) * n + z * hold;
        if (write_hs)    g_Hs[t * H + unit] = hnew;
        if (write_state) g_hstate[unit] = hnew;
        uint32_t off = 4u * (uint32_t)unit;
#pragma unroll
        for (int d = 0; d < CLN; d++)
            asm volatile("st.shared::cluster.f32 [%0], %1;"
                         :: "r"(sh_pbase[p][d] + off), "f"(hnew) : "memory");
    }
    CLUSTER_SYNC_();  // release own stores / acquire peers'
}

__global__ void __cluster_dims__(CLN, 1, 1) __launch_bounds__(SCAN_THREADS, 1)
scan_kernel(const float* __restrict__ eWhh, const float* __restrict__ eBhh,
            const float* __restrict__ dWhh, const float* __restrict__ dBhh,
            int t0, int t1)
{
    int tid = threadIdx.x;
    int l = tid & 31;
    int w = tid >> 5;                 // warp 0..11
    int seg = l >> 3;                 // h segment 0..3
    int row = 8 * w + (l & 7);        // 0..95
    int g = row >> 5, j = row & 31;
    int c = blockIdx.x;               // slice owner id
    int unit = c * SLICE + tid;       // valid when tid < 32

    // this lane's 64-element row segment of both W_hh, packed as f32x2
    const size_t woff = (size_t)(g * H + c * SLICE + j) * H + 64 * seg;
    unsigned long long wE2[32], wD2[32];
    const unsigned long long* ep = (const unsigned long long*)(eWhh + woff);
    const unsigned long long* dp = (const unsigned long long*)(dWhh + woff);
#pragma unroll
    for (int i = 0; i < 32; i++) { wE2[i] = ep[i]; wD2[i] = dp[i]; }

    // init shared state: h (zeros or persisted), biases, remote bases
    if (tid < H) sh_hb[tid] = (t0 == 0) ? 0.f : g_hstate[tid];
    if (tid < 96)  sh_bias[tid] = eBhh[(tid >> 5) * H + c * SLICE + (tid & 31)];
    else if (tid < 192) {
        int q = tid - 96;
        sh_bias[tid] = dBhh[(q >> 5) * H + c * SLICE + (q & 31)];
    }
    if (tid < CLN) {
        sh_pbase[0][tid] = mapa_u32(cvta_smem(&sh_hb[H]), tid);  // dest when p=0
        sh_pbase[1][tid] = mapa_u32(cvta_smem(&sh_hb[0]), tid);  // dest when p=1
    }

    CLUSTER_SYNC_();  // buffers initialized before any peer DSMEM write

    for (int t = t0; t < t1; t++) {
        float ge_r = 0.f, ge_z = 0.f, ge_n = 0.f, gd_r = 0.f, gd_z = 0.f, gd_n = 0.f;
        if (tid < SLICE) {
            const float* gie = g_gi_enc + t * G3 + unit;
            ge_r = gie[0]; ge_z = gie[H]; ge_n = gie[2 * H];
            const float* gid = g_gi_dec + t * G3 + unit;
            gd_r = gid[0]; gd_z = gid[H]; gd_n = gid[2 * H];
        }
        // encoder: read h(0) -> write h(1)
        half_step_reg(wE2, 0, tid, l, w, seg, unit, ge_r, ge_z, ge_n, 0,
                      false, false, t);
        // decoder: read h(1) -> write h(0); record h into g_Hs (+state at end)
        half_step_reg(wD2, 1, tid, l, w, seg, unit, gd_r, gd_z, gd_n, 96,
                      true, (t == t1 - 1), t);
    }

    CLUSTER_SYNC_();  // no CTA exits while peers could still touch its SMEM
}

// ---------------------------------------------------------------------------
// 4) log-softmax fix-up: out[t][v] = logit - log(sumexp[t]) for a row chunk
// ---------------------------------------------------------------------------
__global__ void finalize_kernel(float* __restrict__ out, int row0)
{
    int row = row0 + blockIdx.y;
    int i = blockIdx.x * blockDim.x + threadIdx.x;     // float4 index in row
    if (i >= VOUT / 4) return;
    float lg = logf(g_sumexp[row]);
    float4* o4 = (float4*)(out + (size_t)row * VOUT) + i;
    float4 v = *o4;
    v.x -= lg; v.y -= lg; v.z -= lg; v.w -= lg;
    *o4 = v;
}

// ---------------------------------------------------------------------------
// Side-stream + events, created at static-init time (before the harness's
// memory checkpoints; no device allocation involved).
// ---------------------------------------------------------------------------
struct AsyncRes {
    cudaStream_t s2 = 0;
    cudaEvent_t  evc[NCHUNK];
    cudaEvent_t  evj;
    AsyncRes() {
        int lo = 0, hi = 0;
        cudaDeviceGetStreamPriorityRange(&lo, &hi);     // lo = lowest priority
        cudaStreamCreateWithPriority(&s2, cudaStreamNonBlocking, lo);
        for (int i = 0; i < NCHUNK; i++)
            cudaEventCreateWithFlags(&evc[i], cudaEventDisableTiming);
        cudaEventCreateWithFlags(&evj, cudaEventDisableTiming);
    }
};
static AsyncRes g_async;

// ---------------------------------------------------------------------------
// Launch (graph-capturable: kernel launches + event edges only)
// ---------------------------------------------------------------------------
extern "C" void kernel_launch(void* const* d_in, const int* in_sizes, int n_in,
                              void* d_out, int out_size)
{
    const int*   src      = (const int*)  d_in[0];
    const int*   trg      = (const int*)  d_in[1];
    const float* enc_emb  = (const float*)d_in[2];
    const float* enc_W_ih = (const float*)d_in[3];
    const float* enc_W_hh = (const float*)d_in[4];
    const float* enc_b_ih = (const float*)d_in[5];
    const float* enc_b_hh = (const float*)d_in[6];
    const float* dec_emb  = (const float*)d_in[7];
    const float* dec_W_ih = (const float*)d_in[8];
    const float* dec_W_hh = (const float*)d_in[9];
    const float* dec_b_ih = (const float*)d_in[10];
    const float* dec_b_hh = (const float*)d_in[11];
    const float* out_W    = (const float*)d_in[12];
    const float* out_b    = (const float*)d_in[13];
    float* out = (float*)d_out;

    float *pXe, *pXd, *pGe, *pGd, *pHs;
    cudaGetSymbolAddress((void**)&pXe, g_Xenc);
    cudaGetSymbolAddress((void**)&pXd, g_Xdec);
    cudaGetSymbolAddress((void**)&pGe, g_gi_enc);
    cudaGetSymbolAddress((void**)&pGd, g_gi_dec);
    cudaGetSymbolAddress((void**)&pHs, g_Hs);

    // main stream: gather -> gi GEMMs -> scan chunks (events mark completion)
    gather_kernel<<<T_SEQ, 256>>>(src, trg, enc_emb, dec_emb);
    gemm_kernel<<<dim3(T_SEQ / 128, G3 / 128), 256>>>(pXe, enc_W_ih, enc_b_ih, pGe, G3, 0, 0);
    gemm_kernel<<<dim3(T_SEQ / 128, G3 / 128), 256>>>(pXd, dec_W_ih, dec_b_ih, pGd, G3, 0, 0);

    for (int c = 0; c < NCHUNK; c++) {
        scan_kernel<<<CLN, SCAN_THREADS>>>(enc_W_hh, enc_b_hh, dec_W_hh, dec_b_hh,
                                           c * TCH, (c + 1) * TCH);
        cudaEventRecord(g_async.evc[c], 0);
    }

    // side stream (low priority): per-chunk logits GEMM + log-softmax fix-up,
    // overlapping later scan chunks on the 140 SMs the cluster doesn't use.
    for (int c = 0; c < NCHUNK; c++) {
        cudaStreamWaitEvent(g_async.s2, g_async.evc[c], 0);
        gemm_kernel<<<dim3(TCH / 128, VOUT / 128), 256, 0, g_async.s2>>>(
            pHs + (size_t)c * TCH * H, out_W, out_b,
            out + (size_t)c * TCH * VOUT, VOUT, 1, c * TCH);
        finalize_kernel<<<dim3((VOUT / 4 + 255) / 256, TCH), 256, 0, g_async.s2>>>(
            out, c * TCH);
    }
    cudaEventRecord(g_async.evj, g_async.s2);
    cudaStreamWaitEvent(0, g_async.evj, 0);   // join before returning
}

// round 13
// speedup vs baseline: 1.6449x; 1.6449x over previous
#include <cuda_runtime.h>
#include <cstdint>
#include <math.h>

// Problem constants
#define T_SEQ 2048
#define H     256
#define G3    768          // 3*H gate rows
#define VOUT  32000

// Scan cluster config
#define CLN          8     // cluster size
#define SLICE        32    // hidden units per CTA (H / CLN)
#define SCAN_THREADS 384   // 12 warps; warp w computes rows [8w, 8w+8)
#define HP           272   // padded h pitch: 4 segments of 64, +4 floats apart

// ---------------------------------------------------------------------------
// Device scratch (static __device__ arrays: allocation-free per harness rules)
// ---------------------------------------------------------------------------
__device__ __align__(16) float g_Xenc[T_SEQ * H];
__device__ __align__(16) float g_Xdec[T_SEQ * H];
__device__ __align__(16) float g_gi_enc[T_SEQ * G3];
__device__ __align__(16) float g_gi_dec[T_SEQ * G3];
__device__ __align__(16) float g_Hs[T_SEQ * H];
__device__ __align__(16) float g_sumexp[T_SEQ];

// ---------------------------------------------------------------------------
// PTX helpers
// ---------------------------------------------------------------------------
__device__ __forceinline__ uint32_t cvta_smem(const void* p) {
    return (uint32_t)__cvta_generic_to_shared(p);
}
__device__ __forceinline__ uint32_t mapa_u32(uint32_t laddr, uint32_t rank) {
    uint32_t r;
    asm("mapa.shared::cluster.u32 %0, %1, %2;" : "=r"(r) : "r"(laddr), "r"(rank));
    return r;
}
#define CLUSTER_SYNC_() do { \
    asm volatile("barrier.cluster.arrive.aligned;" ::: "memory"); \
    asm volatile("barrier.cluster.wait.aligned;"   ::: "memory"); \
} while (0)

// packed fp32x2 FMA (Blackwell): d = a*b + c elementwise on 2 packed floats
__device__ __forceinline__ unsigned long long fma2(unsigned long long a,
                                                   unsigned long long b,
                                                   unsigned long long c) {
    unsigned long long d;
    asm("fma.rn.f32x2 %0, %1, %2, %3;" : "=l"(d) : "l"(a), "l"(b), "l"(c));
    return d;
}
__device__ __forceinline__ float2 unpack2(unsigned long long v) {
    float2 r;
    asm("mov.b64 {%0, %1}, %2;" : "=f"(r.x), "=f"(r.y) : "l"(v));
    return r;
}
__device__ __forceinline__ unsigned long long pack_dup(float a) {
    unsigned long long r;
    asm("mov.b64 %0, {%1, %1};" : "=l"(r) : "f"(a));
    return r;
}

// fast gates (MUFU-based; rel err ~1e-6, safe vs 1e-3 tolerance)
__device__ __forceinline__ float fsigmoid(float x) {
    return __fdividef(1.f, 1.f + __expf(-x));     // x->-inf: exp=inf -> 0  OK
}
__device__ __forceinline__ float ftanh(float x) {
    float e = __expf(fminf(-2.f * x, 80.f));      // clamp avoids inf/inf NaN
    return (1.f - e) * __fdividef(1.f, 1.f + e);
}

// ---------------------------------------------------------------------------
// 1) Gather embeddings (+ relu for decoder input) and zero the sum-exp accum.
// ---------------------------------------------------------------------------
__global__ void gather_kernel(const int* __restrict__ src, const int* __restrict__ trg,
                              const float* __restrict__ enc_emb,
                              const float* __restrict__ dec_emb)
{
    int t = blockIdx.x;
    int i = threadIdx.x;           // 256 threads
    int s = src[t];
    int d = trg[t];
    g_Xenc[t * H + i] = enc_emb[(size_t)s * H + i];
    float v = dec_emb[(size_t)d * H + i];
    g_Xdec[t * H + i] = v > 0.f ? v : 0.f;
    if (t < T_SEQ / H) g_sumexp[t * H + i] = 0.f;   // 8 blocks zero all 2048 entries
}

// ---------------------------------------------------------------------------
// 2) fp32 GEMM: C[M][N] = A[M][256] * B[N][256]^T + bias[N]
//    128x128 tiles, BK=16, 256 threads, 8x8 micro-tile, packed FFMA2 inner
//    product (fma.rn.f32x2): 32 fma2/thread/kk instead of 64 FFMA -> ~2x fma
//    throughput. do_lse: per-row sum(exp(c)) into g_sumexp.
// ---------------------------------------------------------------------------
__global__ __launch_bounds__(256)
void gemm_kernel(const float* __restrict__ A, const float* __restrict__ B,
                 const float* __restrict__ bias, float* __restrict__ C,
                 int N, int do_lse)
{
    __shared__ float As[16][132];   // [k][m], padded (132*4 % 16 == 0)
    __shared__ float Bs[16][132];   // [k][n], padded

    int tid = threadIdx.x;
    int tx = tid & 15;              // 0..15 : col group (8 cols)
    int ty = tid >> 4;              // 0..15 : row group (8 rows)
    int bm = blockIdx.x * 128;
    int bn = blockIdx.y * 128;

    int lr  = tid >> 1;             // 0..127 : tile row for loads
    int lk8 = (tid & 1) * 8;        // 0 or 8 : k offset for loads

    const float* Ap = A + (size_t)(bm + lr) * 256 + lk8;
    const float* Bp = B + (size_t)(bn + lr) * 256 + lk8;

    unsigned long long acc2[8][4] = {};   // 8 rows x 4 packed col-pairs

    float4 ra0 = *(const float4*)(Ap + 0);
    float4 ra1 = *(const float4*)(Ap + 4);
    float4 rb0 = *(const float4*)(Bp + 0);
    float4 rb1 = *(const float4*)(Bp + 4);

    for (int kb = 0; kb < 256; kb += 16) {
        __syncthreads();
        As[lk8 + 0][lr] = ra0.x; As[lk8 + 1][lr] = ra0.y; As[lk8 + 2][lr] = ra0.z; As[lk8 + 3][lr] = ra0.w;
        As[lk8 + 4][lr] = ra1.x; As[lk8 + 5][lr] = ra1.y; As[lk8 + 6][lr] = ra1.z; As[lk8 + 7][lr] = ra1.w;
        Bs[lk8 + 0][lr] = rb0.x; Bs[lk8 + 1][lr] = rb0.y; Bs[lk8 + 2][lr] = rb0.z; Bs[lk8 + 3][lr] = rb0.w;
        Bs[lk8 + 4][lr] = rb1.x; Bs[lk8 + 5][lr] = rb1.y; Bs[lk8 + 6][lr] = rb1.z; Bs[lk8 + 7][lr] = rb1.w;
        __syncthreads();
        if (kb < 240) {
            ra0 = *(const float4*)(Ap + kb + 16);
            ra1 = *(const float4*)(Ap + kb + 20);
            rb0 = *(const float4*)(Bp + kb + 16);
            rb1 = *(const float4*)(Bp + kb + 20);
        }
#pragma unroll
        for (int kk = 0; kk < 16; kk++) {
            float4 av0 = *(const float4*)&As[kk][ty * 8];
            float4 av1 = *(const float4*)&As[kk][ty * 8 + 4];
            ulonglong2 bp0 = *(const ulonglong2*)&Bs[kk][tx * 8];       // (b0,b1),(b2,b3)
            ulonglong2 bp1 = *(const ulonglong2*)&Bs[kk][tx * 8 + 4];   // (b4,b5),(b6,b7)
            float a[8] = {av0.x, av0.y, av0.z, av0.w, av1.x, av1.y, av1.z, av1.w};
#pragma unroll
            for (int i = 0; i < 8; i++) {
                unsigned long long aa = pack_dup(a[i]);
                acc2[i][0] = fma2(aa, bp0.x, acc2[i][0]);
                acc2[i][1] = fma2(aa, bp0.y, acc2[i][1]);
                acc2[i][2] = fma2(aa, bp1.x, acc2[i][2]);
                acc2[i][3] = fma2(aa, bp1.y, acc2[i][3]);
            }
        }
    }

    float4 bb0 = *(const float4*)(bias + bn + tx * 8);
    float4 bb1 = *(const float4*)(bias + bn + tx * 8 + 4);
    float bbv[8] = {bb0.x, bb0.y, bb0.z, bb0.w, bb1.x, bb1.y, bb1.z, bb1.w};

#pragma unroll
    for (int i = 0; i < 8; i++) {
        int row = bm + ty * 8 + i;
        float o[8];
#pragma unroll
        for (int j = 0; j < 4; j++) {
            float2 p = unpack2(acc2[i][j]);
            o[2 * j]     = p.x + bbv[2 * j];
            o[2 * j + 1] = p.y + bbv[2 * j + 1];
        }
        float4 o0 = {o[0], o[1], o[2], o[3]};
        float4 o1 = {o[4], o[5], o[6], o[7]};
        float* cp = C + (size_t)row * N + bn + tx * 8;
        *(float4*)(cp)     = o0;
        *(float4*)(cp + 4) = o1;
        if (do_lse) {
            // logits bounded by ~16.1 -> max-free sum-exp is safe in fp32
            float s = 0.f;
#pragma unroll
            for (int j = 0; j < 8; j++) s += __expf(o[j]);
            s += __shfl_xor_sync(0xffffffffu, s, 1);
            s += __shfl_xor_sync(0xffffffffu, s, 2);
            s += __shfl_xor_sync(0xffffffffu, s, 4);
            s += __shfl_xor_sync(0xffffffffu, s, 8);
            if (tx == 0) atomicAdd(&g_sumexp[row], s);
        }
    }
}

// ---------------------------------------------------------------------------
// 3) Sequential GRU scan, single 8-CTA cluster, weights in registers (f32x2).
//    Mapping: warp w -> rows [8w,8w+8); lane l -> row 8w+(l&7), h-segment
//    [64*(l>>3), +64). One accumulator chain per lane, reduction = 2 shuffles.
//    h stored with padded pitch HP=272 (segments 68 floats apart) -> the 4
//    distinct LDS.128 addresses per warp land on disjoint bank groups
//    (conflict-free; unpadded 256-float stride was a 4-way conflict).
//    Sync: barrier.cluster per half-step (proven protocol). Single launch.
// ---------------------------------------------------------------------------
__shared__ __align__(16) float sh_hb[2 * HP];  // replicated h, double buffered
__shared__ float sh_gh[96];                    // row sums (r/z/n x 32 units)
__shared__ float sh_bias[192];                 // [0:96) enc b_hh, [96:192) dec
__shared__ uint32_t sh_pbase[2][CLN];          // remote dest-buffer base addrs

__device__ __forceinline__ void half_step_reg(
    const unsigned long long (&w2)[32], int p, int tid, int l, int w, int seg,
    int unit, int upad, float g_r, float g_z, float g_n, int bias_off,
    bool write_hs, int t)
{
    const ulonglong2* hp2 = (const ulonglong2*)(sh_hb + p * HP + 68 * seg);
    unsigned long long a0 = 0ull, a1 = 0ull, a2 = 0ull, a3 = 0ull;
#pragma unroll
    for (int i = 0; i < 16; i++) {
        ulonglong2 hv = hp2[i];
        if ((i & 1) == 0) {
            a0 = fma2(w2[2 * i],     hv.x, a0);
            a1 = fma2(w2[2 * i + 1], hv.y, a1);
        } else {
            a2 = fma2(w2[2 * i],     hv.x, a2);
            a3 = fma2(w2[2 * i + 1], hv.y, a3);
        }
    }
    float2 f0 = unpack2(a0), f1 = unpack2(a1), f2 = unpack2(a2), f3 = unpack2(a3);
    float v = ((f0.x + f0.y) + (f1.x + f1.y)) + ((f2.x + f2.y) + (f3.x + f3.y));
    // row total: sum the 4 h-segments (lanes l, l^8, l^16, l^24 share a row)
    v += __shfl_xor_sync(0xffffffffu, v, 8);
    v += __shfl_xor_sync(0xffffffffu, v, 16);
    if (l < 8) sh_gh[8 * w + l] = v;
    __syncthreads();

    if (tid < SLICE) {
        float r = fsigmoid(g_r + sh_gh[tid]      + sh_bias[bias_off + tid]);
        float z = fsigmoid(g_z + sh_gh[32 + tid] + sh_bias[bias_off + 32 + tid]);
        float n = ftanh(g_n + r * (sh_gh[64 + tid] + sh_bias[bias_off + 64 + tid]));
        float hold = sh_hb[p * HP + upad];
        float hnew = (1.f - z) * n + z * hold;
        if (write_hs) g_Hs[t * H + unit] = hnew;
        uint32_t off = 4u * (uint32_t)upad;
#pragma unroll
        for (int d = 0; d < CLN; d++)
            asm volatile("st.shared::cluster.f32 [%0], %1;"
                         :: "r"(sh_pbase[p][d] + off), "f"(hnew) : "memory");
    }
    CLUSTER_SYNC_();  // release own stores / acquire peers'
}

__global__ void __cluster_dims__(CLN, 1, 1) __launch_bounds__(SCAN_THREADS, 1)
scan_kernel(const float* __restrict__ eWhh, const float* __restrict__ eBhh,
            const float* __restrict__ dWhh, const float* __restrict__ dBhh)
{
    int tid = threadIdx.x;
    int l = tid & 31;
    int w = tid >> 5;                 // warp 0..11
    int seg = l >> 3;                 // h segment 0..3
    int row = 8 * w + (l & 7);        // 0..95
    int g = row >> 5, j = row & 31;
    int c = blockIdx.x;               // slice owner id
    int unit = c * SLICE + tid;       // valid when tid < 32
    int upad = unit + 4 * (unit >> 6);// padded h index for this unit

    // this lane's 64-element row segment of both W_hh, packed as f32x2
    const size_t woff = (size_t)(g * H + c * SLICE + j) * H + 64 * seg;
    unsigned long long wE2[32], wD2[32];
    const unsigned long long* ep = (const unsigned long long*)(eWhh + woff);
    const unsigned long long* dp = (const unsigned long long*)(dWhh + woff);
#pragma unroll
    for (int i = 0; i < 32; i++) { wE2[i] = ep[i]; wD2[i] = dp[i]; }

    // init shared state
    for (int i = tid; i < 2 * HP; i += SCAN_THREADS) sh_hb[i] = 0.f;
    if (tid < 96)  sh_bias[tid] = eBhh[(tid >> 5) * H + c * SLICE + (tid & 31)];
    else if (tid < 192) {
        int q = tid - 96;
        sh_bias[tid] = dBhh[(q >> 5) * H + c * SLICE + (q & 31)];
    }
    if (tid < CLN) {
        sh_pbase[0][tid] = mapa_u32(cvta_smem(&sh_hb[HP]), tid);  // dest when p=0
        sh_pbase[1][tid] = mapa_u32(cvta_smem(&sh_hb[0]),  tid);  // dest when p=1
    }

    CLUSTER_SYNC_();  // buffers initialized before any peer DSMEM write

    for (int t = 0; t < T_SEQ; t++) {
        float ge_r = 0.f, ge_z = 0.f, ge_n = 0.f, gd_r = 0.f, gd_z = 0.f, gd_n = 0.f;
        if (tid < SLICE) {
            const float* gie = g_gi_enc + t * G3 + unit;
            ge_r = gie[0]; ge_z = gie[H]; ge_n = gie[2 * H];
            const float* gid = g_gi_dec + t * G3 + unit;
            gd_r = gid[0]; gd_z = gid[H]; gd_n = gid[2 * H];
        }
        // encoder: read h(0) -> write h(1)
        half_step_reg(wE2, 0, tid, l, w, seg, unit, upad, ge_r, ge_z, ge_n, 0,
                      false, t);
        // decoder: read h(1) -> write h(0); record h into g_Hs
        half_step_reg(wD2, 1, tid, l, w, seg, unit, upad, gd_r, gd_z, gd_n, 96,
                      true, t);
    }

    CLUSTER_SYNC_();  // no CTA exits while peers could still touch its SMEM
}

// ---------------------------------------------------------------------------
// 4) log-softmax fix-up: out[t][v] = logit - log(sumexp[t])
// ---------------------------------------------------------------------------
__global__ void finalize_kernel(float* __restrict__ out)
{
    int row = blockIdx.y;
    int i = blockIdx.x * blockDim.x + threadIdx.x;     // float4 index in row
    if (i >= VOUT / 4) return;
    float lg = logf(g_sumexp[row]);
    float4* o4 = (float4*)(out + (size_t)row * VOUT) + i;
    float4 v = *o4;
    v.x -= lg; v.y -= lg; v.z -= lg; v.w -= lg;
    *o4 = v;
}

// ---------------------------------------------------------------------------
// Launch (graph-capturable: kernel launches only, strictly serial on stream 0
// -- the scan is latency-critical; nothing may contend with it)
// ---------------------------------------------------------------------------
extern "C" void kernel_launch(void* const* d_in, const int* in_sizes, int n_in,
                              void* d_out, int out_size)
{
    const int*   src      = (const int*)  d_in[0];
    const int*   trg      = (const int*)  d_in[1];
    const float* enc_emb  = (const float*)d_in[2];
    const float* enc_W_ih = (const float*)d_in[3];
    const float* enc_W_hh = (const float*)d_in[4];
    const float* enc_b_ih = (const float*)d_in[5];
    const float* enc_b_hh = (const float*)d_in[6];
    const float* dec_emb  = (const float*)d_in[7];
    const float* dec_W_ih = (const float*)d_in[8];
    const float* dec_W_hh = (const float*)d_in[9];
    const float* dec_b_ih = (const float*)d_in[10];
    const float* dec_b_hh = (const float*)d_in[11];
    const float* out_W    = (const float*)d_in[12];
    const float* out_b    = (const float*)d_in[13];
    float* out = (float*)d_out;

    float *pXe, *pXd, *pGe, *pGd, *pHs;
    cudaGetSymbolAddress((void**)&pXe, g_Xenc);
    cudaGetSymbolAddress((void**)&pXd, g_Xdec);
    cudaGetSymbolAddress((void**)&pGe, g_gi_enc);
    cudaGetSymbolAddress((void**)&pGd, g_gi_dec);
    cudaGetSymbolAddress((void**)&pHs, g_Hs);

    // 1) gather x vectors (+ relu) and zero sum-exp accumulators
    gather_kernel<<<T_SEQ, 256>>>(src, trg, enc_emb, dec_emb);

    // 2) precompute input-side gate pre-activations (parallel over all t)
    gemm_kernel<<<dim3(T_SEQ / 128, G3 / 128), 256>>>(pXe, enc_W_ih, enc_b_ih, pGe, G3, 0);
    gemm_kernel<<<dim3(T_SEQ / 128, G3 / 128), 256>>>(pXd, dec_W_ih, dec_b_ih, pGd, G3, 0);

    // 3) sequential GRU scan (one 8-CTA cluster, weights register-resident)
    scan_kernel<<<CLN, SCAN_THREADS>>>(enc_W_hh, enc_b_hh, dec_W_hh, dec_b_hh);

    // 4) output projection + per-row sum-exp epilogue
    gemm_kernel<<<dim3(T_SEQ / 128, VOUT / 128), 256>>>(pHs, out_W, out_b, out, VOUT, 1);

    // 5) log-softmax fix-up
    finalize_kernel<<<dim3((VOUT / 4 + 255) / 256, T_SEQ), 256>>>(out);
}

// round 14
// speedup vs baseline: 2.0536x; 1.2485x over previous
#include <cuda_runtime.h>
#include <cstdint>
#include <math.h>

// Problem constants
#define T_SEQ 2048
#define H     256
#define G3    768          // 3*H gate rows
#define VOUT  32000

// Scan cluster config
#define CLN          8     // cluster size
#define SLICE        32    // hidden units per CTA (H / CLN)
#define SCAN_THREADS 384   // 12 warps; warp w computes rows [8w, 8w+8)
#define HP           272   // padded h pitch: 4 segments of 64, 68 apart

// ---------------------------------------------------------------------------
// Device scratch (static __device__ arrays: allocation-free per harness rules)
// ---------------------------------------------------------------------------
__device__ __align__(16) float g_Xenc[T_SEQ * H];
__device__ __align__(16) float g_Xdec[T_SEQ * H];
__device__ __align__(16) float g_gi_enc[T_SEQ * G3];
__device__ __align__(16) float g_gi_dec[T_SEQ * G3];
__device__ __align__(16) float g_Hs[T_SEQ * H];
__device__ __align__(16) float g_sumexp[T_SEQ];

// ---------------------------------------------------------------------------
// PTX helpers
// ---------------------------------------------------------------------------
__device__ __forceinline__ uint32_t cvta_smem(const void* p) {
    return (uint32_t)__cvta_generic_to_shared(p);
}
__device__ __forceinline__ uint32_t mapa_u32(uint32_t laddr, uint32_t rank) {
    uint32_t r;
    asm("mapa.shared::cluster.u32 %0, %1, %2;" : "=r"(r) : "r"(laddr), "r"(rank));
    return r;
}
#define CLUSTER_SYNC_() do { \
    asm volatile("barrier.cluster.arrive.aligned;" ::: "memory"); \
    asm volatile("barrier.cluster.wait.aligned;"   ::: "memory"); \
} while (0)

// packed fp32x2 FMA (Blackwell): d = a*b + c elementwise on 2 packed floats
__device__ __forceinline__ unsigned long long fma2(unsigned long long a,
                                                   unsigned long long b,
                                                   unsigned long long c) {
    unsigned long long d;
    asm("fma.rn.f32x2 %0, %1, %2, %3;" : "=l"(d) : "l"(a), "l"(b), "l"(c));
    return d;
}
__device__ __forceinline__ float2 unpack2(unsigned long long v) {
    float2 r;
    asm("mov.b64 {%0, %1}, %2;" : "=f"(r.x), "=f"(r.y) : "l"(v));
    return r;
}
__device__ __forceinline__ unsigned long long pack_dup(float a) {
    unsigned long long r;
    asm("mov.b64 %0, {%1, %1};" : "=l"(r) : "f"(a));
    return r;
}

// fast gates (MUFU-based; rel err ~1e-6, safe vs 1e-3 tolerance)
__device__ __forceinline__ float fsigmoid(float x) {
    return __fdividef(1.f, 1.f + __expf(-x));     // x->-inf: exp=inf -> 0  OK
}
__device__ __forceinline__ float ftanh(float x) {
    float e = __expf(fminf(-2.f * x, 80.f));      // clamp avoids inf/inf NaN
    return (1.f - e) * __fdividef(1.f, 1.f + e);
}

// ---------------------------------------------------------------------------
// 1) Gather embeddings (+ relu for decoder input) and zero the sum-exp accum.
// ---------------------------------------------------------------------------
__global__ void gather_kernel(const int* __restrict__ src, const int* __restrict__ trg,
                              const float* __restrict__ enc_emb,
                              const float* __restrict__ dec_emb)
{
    int t = blockIdx.x;
    int i = threadIdx.x;           // 256 threads
    int s = src[t];
    int d = trg[t];
    g_Xenc[t * H + i] = enc_emb[(size_t)s * H + i];
    float v = dec_emb[(size_t)d * H + i];
    g_Xdec[t * H + i] = v > 0.f ? v : 0.f;
    if (t < T_SEQ / H) g_sumexp[t * H + i] = 0.f;   // 8 blocks zero all 2048 entries
}

// ---------------------------------------------------------------------------
// 2) fp32 GEMM: C[M][N] = A[M][256] * B[N][256]^T + bias[N]
//    128x128 tiles, BK=16, 256 threads, 8x8 micro-tile, packed FFMA2 inner
//    product. __launch_bounds__(256,2): 2 CTAs/SM for latency hiding.
//    do_lse: per-row sum(exp(c)) into g_sumexp.
// ---------------------------------------------------------------------------
__global__ __launch_bounds__(256, 2)
void gemm_kernel(const float* __restrict__ A, const float* __restrict__ B,
                 const float* __restrict__ bias, float* __restrict__ C,
                 int N, int do_lse)
{
    __shared__ float As[16][132];   // [k][m], padded (132*4 % 16 == 0)
    __shared__ float Bs[16][132];   // [k][n], padded

    int tid = threadIdx.x;
    int tx = tid & 15;              // 0..15 : col group (8 cols)
    int ty = tid >> 4;              // 0..15 : row group (8 rows)
    int bm = blockIdx.x * 128;
    int bn = blockIdx.y * 128;

    int lr  = tid >> 1;             // 0..127 : tile row for loads
    int lk8 = (tid & 1) * 8;        // 0 or 8 : k offset for loads

    const float* Ap = A + (size_t)(bm + lr) * 256 + lk8;
    const float* Bp = B + (size_t)(bn + lr) * 256 + lk8;

    unsigned long long acc2[8][4] = {};   // 8 rows x 4 packed col-pairs

    float4 ra0 = *(const float4*)(Ap + 0);
    float4 ra1 = *(const float4*)(Ap + 4);
    float4 rb0 = *(const float4*)(Bp + 0);
    float4 rb1 = *(const float4*)(Bp + 4);

    for (int kb = 0; kb < 256; kb += 16) {
        __syncthreads();
        As[lk8 + 0][lr] = ra0.x; As[lk8 + 1][lr] = ra0.y; As[lk8 + 2][lr] = ra0.z; As[lk8 + 3][lr] = ra0.w;
        As[lk8 + 4][lr] = ra1.x; As[lk8 + 5][lr] = ra1.y; As[lk8 + 6][lr] = ra1.z; As[lk8 + 7][lr] = ra1.w;
        Bs[lk8 + 0][lr] = rb0.x; Bs[lk8 + 1][lr] = rb0.y; Bs[lk8 + 2][lr] = rb0.z; Bs[lk8 + 3][lr] = rb0.w;
        Bs[lk8 + 4][lr] = rb1.x; Bs[lk8 + 5][lr] = rb1.y; Bs[lk8 + 6][lr] = rb1.z; Bs[lk8 + 7][lr] = rb1.w;
        __syncthreads();
        if (kb < 240) {
            ra0 = *(const float4*)(Ap + kb + 16);
            ra1 = *(const float4*)(Ap + kb + 20);
            rb0 = *(const float4*)(Bp + kb + 16);
            rb1 = *(const float4*)(Bp + kb + 20);
        }
#pragma unroll
        for (int kk = 0; kk < 16; kk++) {
            float4 av0 = *(const float4*)&As[kk][ty * 8];
            float4 av1 = *(const float4*)&As[kk][ty * 8 + 4];
            ulonglong2 bp0 = *(const ulonglong2*)&Bs[kk][tx * 8];       // (b0,b1),(b2,b3)
            ulonglong2 bp1 = *(const ulonglong2*)&Bs[kk][tx * 8 + 4];   // (b4,b5),(b6,b7)
            float a[8] = {av0.x, av0.y, av0.z, av0.w, av1.x, av1.y, av1.z, av1.w};
#pragma unroll
            for (int i = 0; i < 8; i++) {
                unsigned long long aa = pack_dup(a[i]);
                acc2[i][0] = fma2(aa, bp0.x, acc2[i][0]);
                acc2[i][1] = fma2(aa, bp0.y, acc2[i][1]);
                acc2[i][2] = fma2(aa, bp1.x, acc2[i][2]);
                acc2[i][3] = fma2(aa, bp1.y, acc2[i][3]);
            }
        }
    }

    float4 bb0 = *(const float4*)(bias + bn + tx * 8);
    float4 bb1 = *(const float4*)(bias + bn + tx * 8 + 4);
    float bbv[8] = {bb0.x, bb0.y, bb0.z, bb0.w, bb1.x, bb1.y, bb1.z, bb1.w};

#pragma unroll
    for (int i = 0; i < 8; i++) {
        int row = bm + ty * 8 + i;
        float o[8];
#pragma unroll
        for (int j = 0; j < 4; j++) {
            float2 p = unpack2(acc2[i][j]);
            o[2 * j]     = p.x + bbv[2 * j];
            o[2 * j + 1] = p.y + bbv[2 * j + 1];
        }
        float4 o0 = {o[0], o[1], o[2], o[3]};
        float4 o1 = {o[4], o[5], o[6], o[7]};
        float* cp = C + (size_t)row * N + bn + tx * 8;
        *(float4*)(cp)     = o0;
        *(float4*)(cp + 4) = o1;
        if (do_lse) {
            // logits bounded by ~16.1 -> max-free sum-exp is safe in fp32
            float s = 0.f;
#pragma unroll
            for (int j = 0; j < 8; j++) s += __expf(o[j]);
            s += __shfl_xor_sync(0xffffffffu, s, 1);
            s += __shfl_xor_sync(0xffffffffu, s, 2);
            s += __shfl_xor_sync(0xffffffffu, s, 4);
            s += __shfl_xor_sync(0xffffffffu, s, 8);
            if (tx == 0) atomicAdd(&g_sumexp[row], s);
        }
    }
}

// ---------------------------------------------------------------------------
// 3) Sequential GRU scan, single 8-CTA cluster, weights in registers (f32x2).
//
//    NEW sync (replaces barrier.cluster in the loop): each broadcast h value
//    is one aligned 8-byte word {epoch:32 | float:32} written with
//    st.shared::cluster.u64. Scalar 8B stores are single-copy atomic, so a
//    consumer spin-load that sees the epoch has the payload in the SAME
//    access -- no fence, no mbarrier, no RMW arrivals, no CCTL.IVALL flush.
//    sh_pair is double-buffered; WAR safety: a producer reaching epoch e+2 on
//    buffer b requires all CTAs' e+1 stores, which each CTA issues only after
//    its matvec finished reading buffer b at epoch e.
//    Epochs: enc(t) polls buf0 for 2t+1, stores 2t+2 to buf1; dec(t) polls
//    buf1 for 2t+2, stores 2t+3 to buf0. Init: buf0 = {1, 0.0f}.
// ---------------------------------------------------------------------------
__shared__ __align__(16) float sh_hb[HP];            // compacted padded h
__shared__ __align__(16) unsigned long long sh_pair[2][H]; // {epoch|h} inbox
__shared__ float sh_gh[96];                          // row sums
__shared__ float sh_bias[192];                       // enc/dec b_hh gates
__shared__ uint32_t sh_pbase[2][CLN];                // remote inbox bases

__device__ __forceinline__ void half_step_reg(
    const unsigned long long (&w2)[32], int p, uint32_t epoch,
    int tid, int l, int w, int seg, int unit, int upad,
    float g_r, float g_z, float g_n, int bias_off, bool write_hs, int t)
{
    // 1) wait for this phase's h values; compact into padded matvec layout
    if (tid < H) {
        uint32_t a = cvta_smem(&sh_pair[p][tid]);
        unsigned long long v;
        do {
            asm volatile("ld.volatile.shared.u64 %0, [%1];" : "=l"(v) : "r"(a));
        } while ((uint32_t)(v >> 32) != epoch);
        sh_hb[tid + 4 * (tid >> 6)] = __uint_as_float((uint32_t)v);
    }
    __syncthreads();

    // 2) matvec (weights in regs, h in conflict-free padded SMEM)
    const ulonglong2* hp2 = (const ulonglong2*)(sh_hb + 68 * seg);
    unsigned long long a0 = 0ull, a1 = 0ull, a2 = 0ull, a3 = 0ull;
#pragma unroll
    for (int i = 0; i < 16; i++) {
        ulonglong2 hv = hp2[i];
        if ((i & 1) == 0) {
            a0 = fma2(w2[2 * i],     hv.x, a0);
            a1 = fma2(w2[2 * i + 1], hv.y, a1);
        } else {
            a2 = fma2(w2[2 * i],     hv.x, a2);
            a3 = fma2(w2[2 * i + 1], hv.y, a3);
        }
    }
    float2 f0 = unpack2(a0), f1 = unpack2(a1), f2 = unpack2(a2), f3 = unpack2(a3);
    float v = ((f0.x + f0.y) + (f1.x + f1.y)) + ((f2.x + f2.y) + (f3.x + f3.y));
    // row total: sum the 4 h-segments (lanes l, l^8, l^16, l^24 share a row)
    v += __shfl_xor_sync(0xffffffffu, v, 8);
    v += __shfl_xor_sync(0xffffffffu, v, 16);
    if (l < 8) sh_gh[8 * w + l] = v;
    __syncthreads();

    // 3) gates + epoch-tagged broadcast (warp 0 only; no barrier needed)
    if (tid < SLICE) {
        float r = fsigmoid(g_r + sh_gh[tid]      + sh_bias[bias_off + tid]);
        float z = fsigmoid(g_z + sh_gh[32 + tid] + sh_bias[bias_off + 32 + tid]);
        float n = ftanh(g_n + r * (sh_gh[64 + tid] + sh_bias[bias_off + 64 + tid]));
        float hold = sh_hb[upad];                  // read BEFORE any overwrite
        float hnew = (1.f - z) * n + z * hold;
        if (write_hs) g_Hs[t * H + unit] = hnew;
        unsigned long long pk =
            ((unsigned long long)(epoch + 1) << 32) | (unsigned long long)__float_as_uint(hnew);
        uint32_t off = 8u * (uint32_t)unit;
#pragma unroll
        for (int d = 0; d < CLN; d++)
            asm volatile("st.shared::cluster.u64 [%0], %1;"
                         :: "r"(sh_pbase[p ^ 1][d] + off), "l"(pk) : "memory");
    }
}

__global__ void __cluster_dims__(CLN, 1, 1) __launch_bounds__(SCAN_THREADS, 1)
scan_kernel(const float* __restrict__ eWhh, const float* __restrict__ eBhh,
            const float* __restrict__ dWhh, const float* __restrict__ dBhh)
{
    int tid = threadIdx.x;
    int l = tid & 31;
    int w = tid >> 5;                 // warp 0..11
    int seg = l >> 3;                 // h segment 0..3
    int row = 8 * w + (l & 7);        // 0..95
    int g = row >> 5, j = row & 31;
    int c = blockIdx.x;               // slice owner id
    int unit = c * SLICE + tid;       // valid when tid < 32
    int upad = unit + 4 * (unit >> 6);// padded h index for this unit

    // this lane's 64-element row segment of both W_hh, packed as f32x2
    const size_t woff = (size_t)(g * H + c * SLICE + j) * H + 64 * seg;
    unsigned long long wE2[32], wD2[32];
    const unsigned long long* ep = (const unsigned long long*)(eWhh + woff);
    const unsigned long long* dp = (const unsigned long long*)(dWhh + woff);
#pragma unroll
    for (int i = 0; i < 32; i++) { wE2[i] = ep[i]; wD2[i] = dp[i]; }

    // init shared state: inbox buf0 = {epoch 1, h=0}, buf1 = 0, biases, bases
    if (tid < H) {
        sh_pair[0][tid] = (1ull << 32);
        sh_pair[1][tid] = 0ull;
    }
    if (tid < 96)  sh_bias[tid] = eBhh[(tid >> 5) * H + c * SLICE + (tid & 31)];
    else if (tid < 192) {
        int q = tid - 96;
        sh_bias[tid] = dBhh[(q >> 5) * H + c * SLICE + (q & 31)];
    }
    if (tid < CLN) {
        sh_pbase[0][tid] = mapa_u32(cvta_smem(&sh_pair[0][0]), tid);
        sh_pbase[1][tid] = mapa_u32(cvta_smem(&sh_pair[1][0]), tid);
    }

    CLUSTER_SYNC_();  // inboxes initialized before any peer DSMEM write

    for (int t = 0; t < T_SEQ; t++) {
        uint32_t ep0 = 2u * (uint32_t)t + 1u;
        float ge_r = 0.f, ge_z = 0.f, ge_n = 0.f, gd_r = 0.f, gd_z = 0.f, gd_n = 0.f;
        if (tid < SLICE) {
            const float* gie = g_gi_enc + t * G3 + unit;
            ge_r = gie[0]; ge_z = gie[H]; ge_n = gie[2 * H];
            const float* gid = g_gi_dec + t * G3 + unit;
            gd_r = gid[0]; gd_z = gid[H]; gd_n = gid[2 * H];
        }
        // encoder: poll buf0@ep0, broadcast to buf1@ep0+1
        half_step_reg(wE2, 0, ep0,     tid, l, w, seg, unit, upad,
                      ge_r, ge_z, ge_n, 0,  false, t);
        // decoder: poll buf1@ep0+1, broadcast to buf0@ep0+2; record h
        half_step_reg(wD2, 1, ep0 + 1, tid, l, w, seg, unit, upad,
                      gd_r, gd_z, gd_n, 96, true,  t);
    }

    CLUSTER_SYNC_();  // no CTA exits while peers could still touch its SMEM
}

// ---------------------------------------------------------------------------
// 4) log-softmax fix-up: out[t][v] = logit - log(sumexp[t])
// ---------------------------------------------------------------------------
__global__ void finalize_kernel(float* __restrict__ out)
{
    int row = blockIdx.y;
    int i = blockIdx.x * blockDim.x + threadIdx.x;     // float4 index in row
    if (i >= VOUT / 4) return;
    float lg = logf(g_sumexp[row]);
    float4* o4 = (float4*)(out + (size_t)row * VOUT) + i;
    float4 v = *o4;
    v.x -= lg; v.y -= lg; v.z -= lg; v.w -= lg;
    *o4 = v;
}

// ---------------------------------------------------------------------------
// Launch (graph-capturable: kernel launches only, strictly serial on stream 0
// -- the scan is latency-bound; nothing may contend with it)
// ---------------------------------------------------------------------------
extern "C" void kernel_launch(void* const* d_in, const int* in_sizes, int n_in,
                              void* d_out, int out_size)
{
    const int*   src      = (const int*)  d_in[0];
    const int*   trg      = (const int*)  d_in[1];
    const float* enc_emb  = (const float*)d_in[2];
    const float* enc_W_ih = (const float*)d_in[3];
    const float* enc_W_hh = (const float*)d_in[4];
    const float* enc_b_ih = (const float*)d_in[5];
    const float* enc_b_hh = (const float*)d_in[6];
    const float* dec_emb  = (const float*)d_in[7];
    const float* dec_W_ih = (const float*)d_in[8];
    const float* dec_W_hh = (const float*)d_in[9];
    const float* dec_b_ih = (const float*)d_in[10];
    const float* dec_b_hh = (const float*)d_in[11];
    const float* out_W    = (const float*)d_in[12];
    const float* out_b    = (const float*)d_in[13];
    float* out = (float*)d_out;

    float *pXe, *pXd, *pGe, *pGd, *pHs;
    cudaGetSymbolAddress((void**)&pXe, g_Xenc);
    cudaGetSymbolAddress((void**)&pXd, g_Xdec);
    cudaGetSymbolAddress((void**)&pGe, g_gi_enc);
    cudaGetSymbolAddress((void**)&pGd, g_gi_dec);
    cudaGetSymbolAddress((void**)&pHs, g_Hs);

    // 1) gather x vectors (+ relu) and zero sum-exp accumulators
    gather_kernel<<<T_SEQ, 256>>>(src, trg, enc_emb, dec_emb);

    // 2) precompute input-side gate pre-activations (parallel over all t)
    gemm_kernel<<<dim3(T_SEQ / 128, G3 / 128), 256>>>(pXe, enc_W_ih, enc_b_ih, pGe, G3, 0);
    gemm_kernel<<<dim3(T_SEQ / 128, G3 / 128), 256>>>(pXd, dec_W_ih, dec_b_ih, pGd, G3, 0);

    // 3) sequential GRU scan (one 8-CTA cluster, epoch-word dataflow sync)
    scan_kernel<<<CLN, SCAN_THREADS>>>(enc_W_hh, enc_b_hh, dec_W_hh, dec_b_hh);

    // 4) output projection + per-row sum-exp epilogue
    gemm_kernel<<<dim3(T_SEQ / 128, VOUT / 128), 256>>>(pHs, out_W, out_b, out, VOUT, 1);

    // 5) log-softmax fix-up
    finalize_kernel<<<dim3((VOUT / 4 + 255) / 256, T_SEQ), 256>>>(out);
}